// round 2
// baseline (speedup 1.0000x reference)
#include <cuda_runtime.h>

#define BB 4
#define CC 256
#define NN 4096
#define DD 32
#define EPSBN 1e-5f

// Scratch (device globals; no allocation)
__device__ float g_q[BB * DD * NN];          // [b][d][n]
__device__ float g_k[BB * DD * NN];          // [b][d][n]
__device__ float g_vt[BB * NN * CC];         // [b][n][c]  (transposed V for coalesced tile loads)

// ---------------------------------------------------------------------------
// Kernel 1: Q,K projections + BN + ReLU.  grid (32, 4), 128 threads.
// Each thread owns one column i; 64 accumulators (32 q + 32 k).
// ---------------------------------------------------------------------------
__global__ __launch_bounds__(128) void qk_proj_kernel(
    const float* __restrict__ x,
    const float* __restrict__ w_q, const float* __restrict__ w_k,
    const float* __restrict__ s1, const float* __restrict__ b1,
    const float* __restrict__ m1, const float* __restrict__ v1,
    const float* __restrict__ s2, const float* __restrict__ b2,
    const float* __restrict__ m2, const float* __restrict__ v2)
{
    extern __shared__ float wqk[];  // [256][64]: per c, 32 wq then 32 wk
    const int b = blockIdx.y;
    const int i = blockIdx.x * 128 + threadIdx.x;

    for (int idx = threadIdx.x; idx < CC * 64; idx += 128) {
        int c = idx >> 6, o = idx & 63;
        wqk[idx] = (o < 32) ? w_q[o * CC + c] : w_k[(o - 32) * CC + c];
    }
    __syncthreads();

    float accq[32], acck[32];
#pragma unroll
    for (int o = 0; o < 32; o++) { accq[o] = 0.f; acck[o] = 0.f; }

    const float* xp = x + (size_t)(b * CC) * NN + i;
#pragma unroll 4
    for (int c = 0; c < CC; c++) {
        float xv = xp[(size_t)c * NN];
        const float4* wr = reinterpret_cast<const float4*>(wqk + (c << 6));
#pragma unroll
        for (int o4 = 0; o4 < 8; o4++) {
            float4 w4 = wr[o4];
            accq[o4 * 4 + 0] = fmaf(w4.x, xv, accq[o4 * 4 + 0]);
            accq[o4 * 4 + 1] = fmaf(w4.y, xv, accq[o4 * 4 + 1]);
            accq[o4 * 4 + 2] = fmaf(w4.z, xv, accq[o4 * 4 + 2]);
            accq[o4 * 4 + 3] = fmaf(w4.w, xv, accq[o4 * 4 + 3]);
        }
#pragma unroll
        for (int o4 = 0; o4 < 8; o4++) {
            float4 w4 = wr[8 + o4];
            acck[o4 * 4 + 0] = fmaf(w4.x, xv, acck[o4 * 4 + 0]);
            acck[o4 * 4 + 1] = fmaf(w4.y, xv, acck[o4 * 4 + 1]);
            acck[o4 * 4 + 2] = fmaf(w4.z, xv, acck[o4 * 4 + 2]);
            acck[o4 * 4 + 3] = fmaf(w4.w, xv, acck[o4 * 4 + 3]);
        }
    }

#pragma unroll
    for (int o = 0; o < 32; o++) {
        float iv1 = s1[o] * rsqrtf(v1[o] + EPSBN);
        float q = fmaxf(fmaf(accq[o], iv1, b1[o] - m1[o] * iv1), 0.f);
        g_q[(size_t)(b * DD + o) * NN + i] = q;
        float iv2 = s2[o] * rsqrtf(v2[o] + EPSBN);
        float k = fmaxf(fmaf(acck[o], iv2, b2[o] - m2[o] * iv2), 0.f);
        g_k[(size_t)(b * DD + o) * NN + i] = k;
    }
}

// ---------------------------------------------------------------------------
// Kernel 2: V projection + BN + ReLU, written TRANSPOSED as g_vt[b][n][c].
// grid (N/64, C/64, B), 256 threads, 64x64 tile, 4x4 micro-tile.
// ---------------------------------------------------------------------------
__global__ __launch_bounds__(256) void v_proj_kernel(
    const float* __restrict__ x, const float* __restrict__ w_v,
    const float* __restrict__ s3, const float* __restrict__ b3,
    const float* __restrict__ m3, const float* __restrict__ v3)
{
    __shared__ float ws[32][65];  // [kc][o], padded
    __shared__ float xs[32][64];  // [kc][i]
    const int b  = blockIdx.z;
    const int o0 = blockIdx.y << 6;
    const int i0 = blockIdx.x << 6;
    const int tx = threadIdx.x & 15;   // -> o (x4)
    const int ty = threadIdx.x >> 4;   // -> i (x4)

    float acc[4][4];
#pragma unroll
    for (int a = 0; a < 4; a++)
#pragma unroll
        for (int bb2 = 0; bb2 < 4; bb2++) acc[a][bb2] = 0.f;

    for (int c0 = 0; c0 < CC; c0 += 32) {
#pragma unroll
        for (int t = 0; t < 8; t++) {
            int idx = threadIdx.x + (t << 8);
            int kc = idx & 31, o = idx >> 5;
            ws[kc][o] = w_v[(o0 + o) * CC + c0 + kc];
        }
#pragma unroll
        for (int t = 0; t < 8; t++) {
            int idx = threadIdx.x + (t << 8);
            int ii = idx & 63, kc = idx >> 6;
            xs[kc][ii] = x[(size_t)(b * CC + c0 + kc) * NN + i0 + ii];
        }
        __syncthreads();
#pragma unroll 8
        for (int kc = 0; kc < 32; kc++) {
            float av[4], bv[4];
#pragma unroll
            for (int k = 0; k < 4; k++) av[k] = ws[kc][(tx << 2) + k];
#pragma unroll
            for (int k = 0; k < 4; k++) bv[k] = xs[kc][(ty << 2) + k];
#pragma unroll
            for (int ii = 0; ii < 4; ii++)
#pragma unroll
                for (int oo = 0; oo < 4; oo++)
                    acc[ii][oo] = fmaf(av[oo], bv[ii], acc[ii][oo]);
        }
        __syncthreads();
    }

    float inv[4], off[4];
#pragma unroll
    for (int oo = 0; oo < 4; oo++) {
        int o = o0 + (tx << 2) + oo;
        float iv = s3[o] * rsqrtf(v3[o] + EPSBN);
        inv[oo] = iv;
        off[oo] = b3[o] - m3[o] * iv;
    }
#pragma unroll
    for (int ii = 0; ii < 4; ii++) {
        int i = i0 + (ty << 2) + ii;
        float4 r;
        r.x = fmaxf(fmaf(acc[ii][0], inv[0], off[0]), 0.f);
        r.y = fmaxf(fmaf(acc[ii][1], inv[1], off[1]), 0.f);
        r.z = fmaxf(fmaf(acc[ii][2], inv[2], off[2]), 0.f);
        r.w = fmaxf(fmaf(acc[ii][3], inv[3], off[3]), 0.f);
        *reinterpret_cast<float4*>(&g_vt[(size_t)(b * NN + i) * CC + o0 + (tx << 2)]) = r;
    }
}

// ---------------------------------------------------------------------------
// Kernel 3: flash attention, fp32, BM=128 queries/block, BN=64 keys/iter.
// grid (32, 4), 512 threads. out = gamma * softmax(Q^T K) V^T + x.
// ---------------------------------------------------------------------------
#define BM 128
#define BN 64
#define NT 512

// Dynamic smem float offsets
#define OFF_SK   0         // 32*64   = 2048
#define OFF_SQ   2048      // 32*128  = 4096
#define OFF_SP   6144      // 128*65  = 8320
#define OFF_PMAX 14464     // 512
#define OFF_PSUM 14976     // 512
#define OFF_SV   15488     // 64*256  = 16384 -> 31872
// epilogue overlay sO[128][257] = 32896 floats -> dyn smem = 131584 B

__global__ __launch_bounds__(NT, 1) void flash_kernel(
    const float* __restrict__ x,
    const float* __restrict__ gamma_p,
    float* __restrict__ out)
{
    extern __shared__ float sm[];
    float* sK   = sm + OFF_SK;
    float* sQ   = sm + OFF_SQ;
    float* sP   = sm + OFF_SP;
    float* pmax = sm + OFF_PMAX;
    float* psum = sm + OFF_PSUM;
    float* sV   = sm + OFF_SV;
    float* sO   = sm;  // overlay, used only in epilogue

    const int b   = blockIdx.y;
    const int i0  = blockIdx.x * BM;
    const int tid = threadIdx.x;
    const int m   = tid & 127;
    const int g   = tid >> 7;   // 0..3

    // Load Q tile [32][128]
    for (int idx = tid; idx < DD * BM; idx += NT)
        sQ[idx] = g_q[(size_t)(b * DD + (idx >> 7)) * NN + i0 + (idx & 127)];

    float O[64];
#pragma unroll
    for (int c = 0; c < 64; c++) O[c] = 0.f;
    float l = 0.f, M = -1e30f;

    __syncthreads();

    const float4* vt4 = reinterpret_cast<const float4*>(g_vt);
    float4* sV4 = reinterpret_cast<float4*>(sV);
    const float4* sK4 = reinterpret_cast<const float4*>(sK);

    for (int it = 0; it < NN / BN; it++) {
        const int j0 = it * BN;
        // Load K tile [32][64] (coalesced)
        for (int idx = tid; idx < DD * BN; idx += NT)
            sK[idx] = g_k[(size_t)(b * DD + (idx >> 6)) * NN + j0 + (idx & 63)];
        // Load V tile [64][256] as float4 (coalesced, conflict-free)
#pragma unroll
        for (int t = 0; t < 8; t++) {
            int idx4 = tid + t * NT;
            int j = idx4 >> 6, c4 = idx4 & 63;
            sV4[idx4] = vt4[(size_t)(b * NN + j0 + j) * 64 + c4];
        }
        __syncthreads();

        // ---- Phase A: S[m][g*16 .. g*16+15] = Q^T K ----
        float s[16];
#pragma unroll
        for (int jj = 0; jj < 16; jj++) s[jj] = 0.f;
#pragma unroll 8
        for (int d = 0; d < 32; d++) {
            float qd = sQ[(d << 7) + m];
            float4 k0 = sK4[(d << 4) + (g << 2) + 0];
            float4 k1 = sK4[(d << 4) + (g << 2) + 1];
            float4 k2 = sK4[(d << 4) + (g << 2) + 2];
            float4 k3 = sK4[(d << 4) + (g << 2) + 3];
            s[0]  = fmaf(qd, k0.x, s[0]);  s[1]  = fmaf(qd, k0.y, s[1]);
            s[2]  = fmaf(qd, k0.z, s[2]);  s[3]  = fmaf(qd, k0.w, s[3]);
            s[4]  = fmaf(qd, k1.x, s[4]);  s[5]  = fmaf(qd, k1.y, s[5]);
            s[6]  = fmaf(qd, k1.z, s[6]);  s[7]  = fmaf(qd, k1.w, s[7]);
            s[8]  = fmaf(qd, k2.x, s[8]);  s[9]  = fmaf(qd, k2.y, s[9]);
            s[10] = fmaf(qd, k2.z, s[10]); s[11] = fmaf(qd, k2.w, s[11]);
            s[12] = fmaf(qd, k3.x, s[12]); s[13] = fmaf(qd, k3.y, s[13]);
            s[14] = fmaf(qd, k3.z, s[14]); s[15] = fmaf(qd, k3.w, s[15]);
        }
        float mx = s[0];
#pragma unroll
        for (int jj = 1; jj < 16; jj++) mx = fmaxf(mx, s[jj]);
        pmax[(g << 7) + m] = mx;
        __syncthreads();
        float rmax = fmaxf(fmaxf(pmax[m], pmax[128 + m]),
                           fmaxf(pmax[256 + m], pmax[384 + m]));
        float newM = fmaxf(M, rmax);
        float alpha = __expf(M - newM);
        M = newM;
        float ps = 0.f;
#pragma unroll
        for (int jj = 0; jj < 16; jj++) {
            float p = __expf(s[jj] - newM);
            ps += p;
            sP[m * 65 + (g << 4) + jj] = p;
        }
        psum[(g << 7) + m] = ps;
        __syncthreads();
        l = l * alpha + (psum[m] + psum[128 + m] + psum[256 + m] + psum[384 + m]);
#pragma unroll
        for (int c = 0; c < 64; c++) O[c] *= alpha;

        // ---- Phase B: O[m][g*64 .. +63] += P[m][:] * V[:, c] ----
#pragma unroll 4
        for (int j = 0; j < BN; j++) {
            float p = sP[m * 65 + j];
            const float4* vrow = reinterpret_cast<const float4*>(sV + j * 256 + (g << 6));
#pragma unroll
            for (int cc = 0; cc < 16; cc++) {
                float4 v4 = vrow[cc];
                O[cc * 4 + 0] = fmaf(p, v4.x, O[cc * 4 + 0]);
                O[cc * 4 + 1] = fmaf(p, v4.y, O[cc * 4 + 1]);
                O[cc * 4 + 2] = fmaf(p, v4.z, O[cc * 4 + 2]);
                O[cc * 4 + 3] = fmaf(p, v4.w, O[cc * 4 + 3]);
            }
        }
        __syncthreads();
    }

    // ---- Epilogue: out = gamma * O/l + x, via smem transpose ----
    float scl = gamma_p[0] / l;
#pragma unroll
    for (int c = 0; c < 64; c++)
        sO[m * 257 + (g << 6) + c] = O[c] * scl;
    __syncthreads();
#pragma unroll 4
    for (int r = 0; r < (BM * CC) / NT; r++) {
        int idx = r * NT + tid;
        int cc = idx >> 7, ii = idx & 127;
        size_t gidx = (size_t)(b * CC + cc) * NN + i0 + ii;
        out[gidx] = sO[ii * 257 + cc] + x[gidx];
    }
}

// ---------------------------------------------------------------------------
extern "C" void kernel_launch(void* const* d_in, const int* in_sizes, int n_in,
                              void* d_out, int out_size)
{
    const float* x   = (const float*)d_in[0];
    const float* w_q = (const float*)d_in[1];
    const float* w_k = (const float*)d_in[2];
    const float* w_v = (const float*)d_in[3];
    const float* s1 = (const float*)d_in[4];
    const float* b1 = (const float*)d_in[5];
    const float* m1 = (const float*)d_in[6];
    const float* v1 = (const float*)d_in[7];
    const float* s2 = (const float*)d_in[8];
    const float* b2 = (const float*)d_in[9];
    const float* m2 = (const float*)d_in[10];
    const float* v2 = (const float*)d_in[11];
    const float* s3 = (const float*)d_in[12];
    const float* b3 = (const float*)d_in[13];
    const float* m3 = (const float*)d_in[14];
    const float* v3 = (const float*)d_in[15];
    const float* gamma = (const float*)d_in[16];
    float* out = (float*)d_out;

    cudaFuncSetAttribute(qk_proj_kernel, cudaFuncAttributeMaxDynamicSharedMemorySize, 65536);
    cudaFuncSetAttribute(flash_kernel,  cudaFuncAttributeMaxDynamicSharedMemorySize, 131584);

    qk_proj_kernel<<<dim3(NN / 128, BB), 128, 65536>>>(
        x, w_q, w_k, s1, b1, m1, v1, s2, b2, m2, v2);
    v_proj_kernel<<<dim3(NN / 64, CC / 64, BB), 256>>>(x, w_v, s3, b3, m3, v3);
    flash_kernel<<<dim3(NN / BM, BB), NT, 131584>>>(x, gamma, out);
}